// round 15
// baseline (speedup 1.0000x reference)
#include <cuda_runtime.h>
#include <cuda_bf16.h>
#include <cstdint>

#define B_    4
#define N_    2048
#define CIN_  256
#define COUT_ 64
#define H_    8
#define ALPHA 0.2f

// ---------------- scratch (__device__ globals; no allocs allowed) -----------
__device__ float g_htf[(size_t)B_ * H_ * N_ * COUT_];   // hidden, tf32-rounded f32
__device__ float g_s1[B_ * H_ * N_];
__device__ float g_s2[B_ * H_ * N_];
__device__ float g_s2max[B_ * H_];
__device__ float g_A1[B_ * H_ * N_];    // exp(s1 - M)
__device__ float g_A2[B_ * H_ * N_];    // exp(0.2 s1 - M)
__device__ float g_B1[B_ * H_ * N_];    // exp(s2)
__device__ float g_B2[B_ * H_ * N_];    // exp(0.2 s2)
__device__ unsigned g_bits[(size_t)B_ * N_ * (N_ / 32)];          // adj bitmask

// ---------------- helpers (sm_80-era PTX only) ------------------------------
__device__ __forceinline__ uint32_t smem_u32(const void* p) {
    uint32_t a;
    asm("{ .reg .u64 t; cvta.to.shared.u64 t, %1; cvt.u32.u64 %0, t; }"
        : "=r"(a) : "l"(p));
    return a;
}
__device__ __forceinline__ uint32_t to_tf32(float x) {
    uint32_t r;
    asm("cvt.rna.tf32.f32 %0, %1;" : "=r"(r) : "f"(x));
    return r;
}
__device__ __forceinline__ void mma_tf32(float* c, const uint32_t* a,
                                         uint32_t b0, uint32_t b1) {
    asm volatile("mma.sync.aligned.m16n8k8.row.col.f32.tf32.tf32.f32 "
                 "{%0,%1,%2,%3}, {%4,%5,%6,%7}, {%8,%9}, {%0,%1,%2,%3};"
                 : "+f"(c[0]), "+f"(c[1]), "+f"(c[2]), "+f"(c[3])
                 : "r"(a[0]), "r"(a[1]), "r"(a[2]), "r"(a[3]), "r"(b0), "r"(b1));
}
__device__ __forceinline__ void cp_async16(uint32_t dst, const void* src) {
    asm volatile("cp.async.cg.shared.global [%0], [%1], 16;"
                 :: "r"(dst), "l"(src) : "memory");
}
#define CP_COMMIT() asm volatile("cp.async.commit_group;" ::: "memory")
#define CP_WAIT0()  asm volatile("cp.async.wait_group 0;" ::: "memory")

// weight: exp(leaky(s1+s2)-M) = max(A1*B1, A2*B2)
__device__ __forceinline__ float wfun(float A1, float A2,
                                      float f1, float f2, unsigned bit) {
    float w = fmaxf(A1 * f1, A2 * f2);
    return bit ? w : 0.f;
}

// ---------------------------------------------------------------------------
// Kernel 1 (tf32 MMA): hidden = x @ W^T, fused s1/s2 scores.  (round-14 proven)
// ---------------------------------------------------------------------------
#define GP 36

__global__ void __launch_bounds__(256) gemm_hidden_tc(const float* __restrict__ x,
                                                      const float* __restrict__ Wf,
                                                      const float* __restrict__ av) {
    __shared__ uint32_t xs[64 * GP];
    __shared__ uint32_t ws[256 * GP];
    __shared__ float a1s[256], a2s[256];

    const int b  = blockIdx.z;
    const int yg = blockIdx.y;
    const int m0 = blockIdx.x * 64;
    const int t = threadIdx.x, wid = t >> 5, lane = t & 31;
    const int la = lane & 3, gq = lane >> 2;
    const int hg  = wid >> 1;
    const int head = yg * 4 + hg;
    const int mt0 = (wid & 1) * 32;

    {
        int hl = t >> 6, c = t & 63;
        a1s[t] = av[(yg * 4 + hl) * 128 + c];
        a2s[t] = av[(yg * 4 + hl) * 128 + 64 + c];
    }

    const float* xb = x + (size_t)b * N_ * CIN_;
    float acc[2][8][4] = {};

    for (int k0 = 0; k0 < CIN_; k0 += 32) {
#pragma unroll
        for (int r = 0; r < 2; r++) {
            int f = t + r * 256;
            int row = f >> 3, c4 = (f & 7) * 4;
            float4 v = *(const float4*)&xb[(size_t)(m0 + row) * CIN_ + k0 + c4];
            uint4 u = make_uint4(to_tf32(v.x), to_tf32(v.y), to_tf32(v.z), to_tf32(v.w));
            *(uint4*)&xs[row * GP + c4] = u;
        }
#pragma unroll
        for (int r = 0; r < 8; r++) {
            int f = t + r * 256;
            int row = f >> 3, c4 = (f & 7) * 4;
            float4 w = *(const float4*)&Wf[(size_t)(yg * 256 + row) * CIN_ + k0 + c4];
            uint4 u = make_uint4(to_tf32(w.x), to_tf32(w.y), to_tf32(w.z), to_tf32(w.w));
            *(uint4*)&ws[row * GP + c4] = u;
        }
        __syncthreads();

#pragma unroll
        for (int ks = 0; ks < 4; ks++) {
            const int kk = ks * 8;
            uint32_t af[2][4];
#pragma unroll
            for (int mt = 0; mt < 2; mt++) {
                int br = mt0 + mt * 16 + gq;
                af[mt][0] = xs[br * GP + kk + la];
                af[mt][1] = xs[(br + 8) * GP + kk + la];
                af[mt][2] = xs[br * GP + kk + la + 4];
                af[mt][3] = xs[(br + 8) * GP + kk + la + 4];
            }
#pragma unroll
            for (int q = 0; q < 8; q++) {
                int n = hg * 64 + q * 8 + gq;
                uint32_t b0 = ws[n * GP + kk + la];
                uint32_t b1 = ws[n * GP + kk + la + 4];
                mma_tf32(acc[0][q], af[0], b0, b1);
                mma_tf32(acc[1][q], af[1], b0, b1);
            }
        }
        __syncthreads();
    }

    const int bh = b * H_ + head;
    const size_t obase = (size_t)bh * N_ * COUT_;
    float p1[4] = {0.f, 0.f, 0.f, 0.f};
    float p2[4] = {0.f, 0.f, 0.f, 0.f};
#pragma unroll
    for (int mt = 0; mt < 2; mt++) {
        int r0 = mt0 + mt * 16 + gq;
#pragma unroll
        for (int q = 0; q < 8; q++) {
            int col = q * 8 + la * 2;
            float a1x = a1s[hg * 64 + col], a1y = a1s[hg * 64 + col + 1];
            float a2x = a2s[hg * 64 + col], a2y = a2s[hg * 64 + col + 1];
            p1[mt * 2 + 0] += acc[mt][q][0] * a1x + acc[mt][q][1] * a1y;
            p2[mt * 2 + 0] += acc[mt][q][0] * a2x + acc[mt][q][1] * a2y;
            p1[mt * 2 + 1] += acc[mt][q][2] * a1x + acc[mt][q][3] * a1y;
            p2[mt * 2 + 1] += acc[mt][q][2] * a2x + acc[mt][q][3] * a2y;
            float2 h0, h1;
            h0.x = __uint_as_float(to_tf32(acc[mt][q][0]));
            h0.y = __uint_as_float(to_tf32(acc[mt][q][1]));
            h1.x = __uint_as_float(to_tf32(acc[mt][q][2]));
            h1.y = __uint_as_float(to_tf32(acc[mt][q][3]));
            *(float2*)&g_htf[obase + (size_t)(m0 + r0) * COUT_ + col] = h0;
            *(float2*)&g_htf[obase + (size_t)(m0 + r0 + 8) * COUT_ + col] = h1;
        }
    }
#pragma unroll
    for (int off = 1; off <= 2; off <<= 1) {
#pragma unroll
        for (int i = 0; i < 4; i++) {
            p1[i] += __shfl_xor_sync(0xffffffffu, p1[i], off);
            p2[i] += __shfl_xor_sync(0xffffffffu, p2[i], off);
        }
    }
    if (la == 0) {
#pragma unroll
        for (int mt = 0; mt < 2; mt++) {
#pragma unroll
            for (int hf = 0; hf < 2; hf++) {
                int r = mt0 + mt * 16 + hf * 8 + gq;
                g_s1[bh * N_ + m0 + r] = p1[mt * 2 + hf];
                g_s2[bh * N_ + m0 + r] = p2[mt * 2 + hf];
            }
        }
    }
}

// ---------------------------------------------------------------------------
// Kernel 2a: per (b,h) s2 max reduce (grid 32, cheap)
// ---------------------------------------------------------------------------
__global__ void s2max_k() {
    __shared__ float red[256];
    int bh = blockIdx.x;
    const float* s2 = g_s2 + bh * N_;
    float m = -1e30f;
    for (int j = threadIdx.x; j < N_; j += 256) m = fmaxf(m, s2[j]);
    red[threadIdx.x] = m;
    __syncthreads();
    for (int s = 128; s > 0; s >>= 1) {
        if (threadIdx.x < s) red[threadIdx.x] = fmaxf(red[threadIdx.x], red[threadIdx.x + s]);
        __syncthreads();
    }
    if (threadIdx.x == 0) g_s2max[bh] = red[0];
}

// ---------------------------------------------------------------------------
// Kernel 2b: factor precompute, 1 element/thread (grid B*H*8)
// ---------------------------------------------------------------------------
__global__ void factors_k() {
    int bh  = blockIdx.x >> 3;
    int j   = (blockIdx.x & 7) * 256 + threadIdx.x;
    int idx = bh * N_ + j;
    float s1v = g_s1[idx], s2v = g_s2[idx];
    float s2m = g_s2max[bh];
    float e = s1v + s2m;
    float M = (e >= 0.f) ? e : ALPHA * e;
    g_A1[idx] = __expf(s1v - M);
    g_A2[idx] = __expf(ALPHA * s1v - M);
    g_B1[idx] = __expf(s2v);
    g_B2[idx] = __expf(ALPHA * s2v);
}

// ---------------------------------------------------------------------------
// Kernel 3: adj -> bitmask, 4 words per loop iteration (MLP 4)
// ---------------------------------------------------------------------------
__global__ void adj_bits_k(const int* __restrict__ adj) {
    int wid  = threadIdx.x >> 5, lane = threadIdx.x & 31;
    int row  = blockIdx.x * 8 + wid;
    const int* ap = adj + (size_t)row * N_;
    unsigned* bp  = g_bits + (size_t)row * (N_ / 32);
#pragma unroll 4
    for (int w2 = 0; w2 < N_ / 128; w2++) {
        int v0 = ap[w2 * 128 + lane];
        int v1 = ap[w2 * 128 + 32 + lane];
        int v2 = ap[w2 * 128 + 64 + lane];
        int v3 = ap[w2 * 128 + 96 + lane];
        unsigned m0 = __ballot_sync(0xffffffffu, v0 > 0);
        unsigned m1 = __ballot_sync(0xffffffffu, v1 > 0);
        unsigned m2 = __ballot_sync(0xffffffffu, v2 > 0);
        unsigned m3 = __ballot_sync(0xffffffffu, v3 > 0);
        if (lane == 0) {
            bp[w2 * 4 + 0] = m0; bp[w2 * 4 + 1] = m1;
            bp[w2 * 4 + 2] = m2; bp[w2 * 4 + 3] = m3;
        }
    }
}

// ---------------------------------------------------------------------------
// Kernel 4: tf32 MMA AV (round-12 structure). EXPERIMENT: launch_bounds(256,4)
// targets 64 regs -> 4 CTAs/SM (smem 54KB x 4 = 216KB fits).
// ---------------------------------------------------------------------------
#define BPITCH   72
#define BUF_FL   (64 * BPITCH)
#define OFF_BB   0
#define OFF_B1F  36864
#define OFF_B2F  45056
#define OFF_WSUM 53248
#define OFF_BIAS 53760
#define SMEM_TOTAL 54016

__global__ void __launch_bounds__(256, 4) attn_av_mma(const float* __restrict__ bias,
                                                      float* __restrict__ out) {
    extern __shared__ char smem[];
    const uint32_t sb = smem_u32(smem);
    const int b = blockIdx.z, h = blockIdx.y, i0 = blockIdx.x * 128;
    const int bh = b * H_ + h;
    const int t = threadIdx.x, wid = t >> 5, lane = t & 31;

    float* wsum_s = (float*)(smem + OFF_WSUM);
    float* b1f    = (float*)(smem + OFF_B1F);
    float* b2f    = (float*)(smem + OFF_B2F);
    float* bias_s = (float*)(smem + OFF_BIAS);
    float* Bbuf   = (float*)(smem + OFF_BB);
    if (t < 16) *(float4*)&bias_s[t * 4] = *(const float4*)&bias[h * COUT_ + t * 4];

    // prologue: stage factor arrays (visible after first loop sync)
    {
        const float* B1g = g_B1 + bh * N_;
        const float* B2g = g_B2 + bh * N_;
#pragma unroll
        for (int r = 0; r < 2; r++) {
            int q = (t + r * 256) * 4;
            *(float4*)&b1f[q] = *(const float4*)&B1g[q];
            *(float4*)&b2f[q] = *(const float4*)&B2g[q];
        }
    }

    const int m0 = wid * 16;
    const int r0loc = m0 + (lane >> 2);
    const int r1loc = r0loc + 8;
    const int la = lane & 3;
    const int gn = lane >> 2;
    const float A1_0 = g_A1[bh * N_ + i0 + r0loc];
    const float A2_0 = g_A2[bh * N_ + i0 + r0loc];
    const float A1_1 = g_A1[bh * N_ + i0 + r1loc];
    const float A2_1 = g_A2[bh * N_ + i0 + r1loc];
    float lsum0 = 0.f, lsum1 = 0.f;

    const float* hT = g_htf + (size_t)bh * N_ * COUT_;
    const unsigned* bpr0 = g_bits + ((size_t)(b * N_ + i0 + r0loc)) * (N_ / 32);
    const unsigned* bpr1 = bpr0 + (size_t)8 * (N_ / 32);   // r1loc = r0loc + 8

    float acc[8][4] = {};

    // stage jt=0 into buffer 0
    {
#pragma unroll
        for (int r = 0; r < 4; r++) {
            int idx = t + r * 256;
            int row = idx >> 4, cq = idx & 15;
            cp_async16(sb + OFF_BB + (uint32_t)(row * BPITCH * 4 + cq * 16),
                       hT + (size_t)row * COUT_ + cq * 4);
        }
        CP_COMMIT();
    }

    for (int jt = 0; jt < 32; jt++) {
        const int j0 = jt * 64;
        const float* Bt = Bbuf + (jt & 1) * BUF_FL;

        CP_WAIT0();
        __syncthreads();

        if (jt + 1 < 32) {
            const int j0n = j0 + 64;
            const uint32_t bufn = sb + OFF_BB + (uint32_t)((jt + 1) & 1) * (BUF_FL * 4);
#pragma unroll
            for (int r = 0; r < 4; r++) {
                int idx = t + r * 256;
                int row = idx >> 4, cq = idx & 15;
                cp_async16(bufn + (uint32_t)(row * BPITCH * 4 + cq * 16),
                           hT + (size_t)(j0n + row) * COUT_ + cq * 4);
            }
            CP_COMMIT();
        }

        uint2 bitsA = *(const uint2*)&bpr0[jt * 2];
        uint2 bitsB = *(const uint2*)&bpr1[jt * 2];

#pragma unroll
        for (int ks = 0; ks < 8; ks++) {
            const int jl = ks * 8 + la;
            float f1x = b1f[j0 + jl],     f2x = b2f[j0 + jl];
            float f1y = b1f[j0 + jl + 4], f2y = b2f[j0 + jl + 4];
            unsigned wrd0 = (ks < 4) ? bitsA.x : bitsA.y;
            unsigned wrd1 = (ks < 4) ? bitsB.x : bitsB.y;
            const int sh = (ks & 3) * 8 + la;

            float wa0 = wfun(A1_0, A2_0, f1x, f2x, (wrd0 >> sh) & 1u);
            float wa2 = wfun(A1_0, A2_0, f1y, f2y, (wrd0 >> (sh + 4)) & 1u);
            float wb0 = wfun(A1_1, A2_1, f1x, f2x, (wrd1 >> sh) & 1u);
            float wb2 = wfun(A1_1, A2_1, f1y, f2y, (wrd1 >> (sh + 4)) & 1u);
            lsum0 += wa0 + wa2;
            lsum1 += wb0 + wb2;

            uint32_t afr[4];
            afr[0] = to_tf32(wa0);
            afr[1] = to_tf32(wb0);
            afr[2] = to_tf32(wa2);
            afr[3] = to_tf32(wb2);

            const float* Brow0 = Bt + (ks * 8 + la) * BPITCH + gn;
            const float* Brow1 = Brow0 + 4 * BPITCH;
#pragma unroll
            for (int q = 0; q < 8; q++) {
                uint32_t bf0 = __float_as_uint(Brow0[q * 8]);
                uint32_t bf1 = __float_as_uint(Brow1[q * 8]);
                mma_tf32(acc[q], afr, bf0, bf1);
            }
        }
    }

    lsum0 += __shfl_xor_sync(0xffffffffu, lsum0, 1);
    lsum0 += __shfl_xor_sync(0xffffffffu, lsum0, 2);
    lsum1 += __shfl_xor_sync(0xffffffffu, lsum1, 1);
    lsum1 += __shfl_xor_sync(0xffffffffu, lsum1, 2);
    if (la == 0) {
        wsum_s[r0loc] = lsum0;
        wsum_s[r1loc] = lsum1;
    }
    __syncthreads();

    const float inv0 = 1.f / wsum_s[r0loc];
    const float inv1 = 1.f / wsum_s[r1loc];
    float* op0 = out + ((size_t)(b * N_ + i0 + r0loc)) * (H_ * COUT_) + h * COUT_;
    float* op1 = out + ((size_t)(b * N_ + i0 + r1loc)) * (H_ * COUT_) + h * COUT_;
#pragma unroll
    for (int q = 0; q < 8; q++) {
        int col = q * 8 + la * 2;
        float bx = bias_s[col], by = bias_s[col + 1];
        float2 o0, o1;
        o0.x = fmaxf(acc[q][0] * inv0 + bx, 0.f);
        o0.y = fmaxf(acc[q][1] * inv0 + by, 0.f);
        o1.x = fmaxf(acc[q][2] * inv1 + bx, 0.f);
        o1.y = fmaxf(acc[q][3] * inv1 + by, 0.f);
        *(float2*)&op0[col] = o0;
        *(float2*)&op1[col] = o1;
    }
}

// ---------------------------------------------------------------------------
extern "C" void kernel_launch(void* const* d_in, const int* in_sizes, int n_in,
                              void* d_out, int out_size) {
    const float* x    = (const float*)d_in[0];
    const int*   adj  = (const int*)  d_in[1];
    const float* W    = (const float*)d_in[2];
    const float* a    = (const float*)d_in[3];
    const float* bias = (const float*)d_in[4];
    float* out = (float*)d_out;

    cudaFuncSetAttribute(attn_av_mma, cudaFuncAttributeMaxDynamicSharedMemorySize,
                         SMEM_TOTAL);

    adj_bits_k<<<(B_ * N_) / 8, 256>>>(adj);

    dim3 g1(N_ / 64, 2, B_);
    gemm_hidden_tc<<<g1, 256>>>(x, W, a);

    s2max_k<<<B_ * H_, 256>>>();
    factors_k<<<B_ * H_ * 8, 256>>>();

    dim3 g4(N_ / 128, H_, B_);
    attn_av_mma<<<g4, 256, SMEM_TOTAL>>>(bias, out);
}

// round 17
// speedup vs baseline: 1.0727x; 1.0727x over previous
#include <cuda_runtime.h>
#include <cuda_bf16.h>
#include <cstdint>

#define B_    4
#define N_    2048
#define CIN_  256
#define COUT_ 64
#define H_    8
#define ALPHA 0.2f

// ---------------- scratch (__device__ globals; no allocs allowed) -----------
__device__ float g_htf[(size_t)B_ * H_ * N_ * COUT_];   // hidden, tf32-rounded f32
__device__ float g_s1[B_ * H_ * N_];
__device__ float g_s2[B_ * H_ * N_];
__device__ float g_s2max[B_ * H_];
__device__ float g_A1[B_ * H_ * N_];            // exp(s1 - M)
__device__ float g_A2[B_ * H_ * N_];            // exp(0.2 s1 - M)
__device__ float2 g_B12[B_ * H_ * N_];          // {exp(s2), exp(0.2 s2)} interleaved
__device__ unsigned g_bits[(size_t)B_ * N_ * (N_ / 32)];          // adj bitmask

// ---------------- helpers (sm_80-era PTX only) ------------------------------
__device__ __forceinline__ uint32_t smem_u32(const void* p) {
    uint32_t a;
    asm("{ .reg .u64 t; cvta.to.shared.u64 t, %1; cvt.u32.u64 %0, t; }"
        : "=r"(a) : "l"(p));
    return a;
}
__device__ __forceinline__ uint32_t to_tf32(float x) {
    uint32_t r;
    asm("cvt.rna.tf32.f32 %0, %1;" : "=r"(r) : "f"(x));
    return r;
}
__device__ __forceinline__ void mma_tf32(float* c, const uint32_t* a,
                                         uint32_t b0, uint32_t b1) {
    asm volatile("mma.sync.aligned.m16n8k8.row.col.f32.tf32.tf32.f32 "
                 "{%0,%1,%2,%3}, {%4,%5,%6,%7}, {%8,%9}, {%0,%1,%2,%3};"
                 : "+f"(c[0]), "+f"(c[1]), "+f"(c[2]), "+f"(c[3])
                 : "r"(a[0]), "r"(a[1]), "r"(a[2]), "r"(a[3]), "r"(b0), "r"(b1));
}
__device__ __forceinline__ void cp_async16(uint32_t dst, const void* src) {
    asm volatile("cp.async.cg.shared.global [%0], [%1], 16;"
                 :: "r"(dst), "l"(src) : "memory");
}
#define CP_COMMIT() asm volatile("cp.async.commit_group;" ::: "memory")
#define CP_WAIT0()  asm volatile("cp.async.wait_group 0;" ::: "memory")

// weight: exp(leaky(s1+s2)-M) = max(A1*B1, A2*B2)
__device__ __forceinline__ float wfun(float A1, float A2,
                                      float f1, float f2, unsigned bit) {
    float w = fmaxf(A1 * f1, A2 * f2);
    return bit ? w : 0.f;
}

// ---------------------------------------------------------------------------
// Kernel 1 (tf32 MMA): hidden = x @ W^T, fused s1/s2 scores.  (round-14 proven)
// ---------------------------------------------------------------------------
#define GP 36

__global__ void __launch_bounds__(256) gemm_hidden_tc(const float* __restrict__ x,
                                                      const float* __restrict__ Wf,
                                                      const float* __restrict__ av) {
    __shared__ uint32_t xs[64 * GP];
    __shared__ uint32_t ws[256 * GP];
    __shared__ float a1s[256], a2s[256];

    const int b  = blockIdx.z;
    const int yg = blockIdx.y;
    const int m0 = blockIdx.x * 64;
    const int t = threadIdx.x, wid = t >> 5, lane = t & 31;
    const int la = lane & 3, gq = lane >> 2;
    const int hg  = wid >> 1;
    const int head = yg * 4 + hg;
    const int mt0 = (wid & 1) * 32;

    {
        int hl = t >> 6, c = t & 63;
        a1s[t] = av[(yg * 4 + hl) * 128 + c];
        a2s[t] = av[(yg * 4 + hl) * 128 + 64 + c];
    }

    const float* xb = x + (size_t)b * N_ * CIN_;
    float acc[2][8][4] = {};

    for (int k0 = 0; k0 < CIN_; k0 += 32) {
#pragma unroll
        for (int r = 0; r < 2; r++) {
            int f = t + r * 256;
            int row = f >> 3, c4 = (f & 7) * 4;
            float4 v = *(const float4*)&xb[(size_t)(m0 + row) * CIN_ + k0 + c4];
            uint4 u = make_uint4(to_tf32(v.x), to_tf32(v.y), to_tf32(v.z), to_tf32(v.w));
            *(uint4*)&xs[row * GP + c4] = u;
        }
#pragma unroll
        for (int r = 0; r < 8; r++) {
            int f = t + r * 256;
            int row = f >> 3, c4 = (f & 7) * 4;
            float4 w = *(const float4*)&Wf[(size_t)(yg * 256 + row) * CIN_ + k0 + c4];
            uint4 u = make_uint4(to_tf32(w.x), to_tf32(w.y), to_tf32(w.z), to_tf32(w.w));
            *(uint4*)&ws[row * GP + c4] = u;
        }
        __syncthreads();

#pragma unroll
        for (int ks = 0; ks < 4; ks++) {
            const int kk = ks * 8;
            uint32_t af[2][4];
#pragma unroll
            for (int mt = 0; mt < 2; mt++) {
                int br = mt0 + mt * 16 + gq;
                af[mt][0] = xs[br * GP + kk + la];
                af[mt][1] = xs[(br + 8) * GP + kk + la];
                af[mt][2] = xs[br * GP + kk + la + 4];
                af[mt][3] = xs[(br + 8) * GP + kk + la + 4];
            }
#pragma unroll
            for (int q = 0; q < 8; q++) {
                int n = hg * 64 + q * 8 + gq;
                uint32_t b0 = ws[n * GP + kk + la];
                uint32_t b1 = ws[n * GP + kk + la + 4];
                mma_tf32(acc[0][q], af[0], b0, b1);
                mma_tf32(acc[1][q], af[1], b0, b1);
            }
        }
        __syncthreads();
    }

    const int bh = b * H_ + head;
    const size_t obase = (size_t)bh * N_ * COUT_;
    float p1[4] = {0.f, 0.f, 0.f, 0.f};
    float p2[4] = {0.f, 0.f, 0.f, 0.f};
#pragma unroll
    for (int mt = 0; mt < 2; mt++) {
        int r0 = mt0 + mt * 16 + gq;
#pragma unroll
        for (int q = 0; q < 8; q++) {
            int col = q * 8 + la * 2;
            float a1x = a1s[hg * 64 + col], a1y = a1s[hg * 64 + col + 1];
            float a2x = a2s[hg * 64 + col], a2y = a2s[hg * 64 + col + 1];
            p1[mt * 2 + 0] += acc[mt][q][0] * a1x + acc[mt][q][1] * a1y;
            p2[mt * 2 + 0] += acc[mt][q][0] * a2x + acc[mt][q][1] * a2y;
            p1[mt * 2 + 1] += acc[mt][q][2] * a1x + acc[mt][q][3] * a1y;
            p2[mt * 2 + 1] += acc[mt][q][2] * a2x + acc[mt][q][3] * a2y;
            float2 h0, h1;
            h0.x = __uint_as_float(to_tf32(acc[mt][q][0]));
            h0.y = __uint_as_float(to_tf32(acc[mt][q][1]));
            h1.x = __uint_as_float(to_tf32(acc[mt][q][2]));
            h1.y = __uint_as_float(to_tf32(acc[mt][q][3]));
            *(float2*)&g_htf[obase + (size_t)(m0 + r0) * COUT_ + col] = h0;
            *(float2*)&g_htf[obase + (size_t)(m0 + r0 + 8) * COUT_ + col] = h1;
        }
    }
#pragma unroll
    for (int off = 1; off <= 2; off <<= 1) {
#pragma unroll
        for (int i = 0; i < 4; i++) {
            p1[i] += __shfl_xor_sync(0xffffffffu, p1[i], off);
            p2[i] += __shfl_xor_sync(0xffffffffu, p2[i], off);
        }
    }
    if (la == 0) {
#pragma unroll
        for (int mt = 0; mt < 2; mt++) {
#pragma unroll
            for (int hf = 0; hf < 2; hf++) {
                int r = mt0 + mt * 16 + hf * 8 + gq;
                g_s1[bh * N_ + m0 + r] = p1[mt * 2 + hf];
                g_s2[bh * N_ + m0 + r] = p2[mt * 2 + hf];
            }
        }
    }
}

// ---------------------------------------------------------------------------
// Kernel 2a: per (b,h) s2 max reduce (grid 32, cheap)
// ---------------------------------------------------------------------------
__global__ void s2max_k() {
    __shared__ float red[256];
    int bh = blockIdx.x;
    const float* s2 = g_s2 + bh * N_;
    float m = -1e30f;
    for (int j = threadIdx.x; j < N_; j += 256) m = fmaxf(m, s2[j]);
    red[threadIdx.x] = m;
    __syncthreads();
    for (int s = 128; s > 0; s >>= 1) {
        if (threadIdx.x < s) red[threadIdx.x] = fmaxf(red[threadIdx.x], red[threadIdx.x + s]);
        __syncthreads();
    }
    if (threadIdx.x == 0) g_s2max[bh] = red[0];
}

// ---------------------------------------------------------------------------
// Kernel 2b: factor precompute, 1 element/thread; B-factors written interleaved
// ---------------------------------------------------------------------------
__global__ void factors_k() {
    int bh  = blockIdx.x >> 3;
    int j   = (blockIdx.x & 7) * 256 + threadIdx.x;
    int idx = bh * N_ + j;
    float s1v = g_s1[idx], s2v = g_s2[idx];
    float s2m = g_s2max[bh];
    float e = s1v + s2m;
    float M = (e >= 0.f) ? e : ALPHA * e;
    g_A1[idx] = __expf(s1v - M);
    g_A2[idx] = __expf(ALPHA * s1v - M);
    g_B12[idx] = make_float2(__expf(s2v), __expf(ALPHA * s2v));
}

// ---------------------------------------------------------------------------
// Kernel 3: adj -> bitmask, 4 words per loop iteration (MLP 4)
// ---------------------------------------------------------------------------
__global__ void adj_bits_k(const int* __restrict__ adj) {
    int wid  = threadIdx.x >> 5, lane = threadIdx.x & 31;
    int row  = blockIdx.x * 8 + wid;
    const int* ap = adj + (size_t)row * N_;
    unsigned* bp  = g_bits + (size_t)row * (N_ / 32);
#pragma unroll 4
    for (int w2 = 0; w2 < N_ / 128; w2++) {
        int v0 = ap[w2 * 128 + lane];
        int v1 = ap[w2 * 128 + 32 + lane];
        int v2 = ap[w2 * 128 + 64 + lane];
        int v3 = ap[w2 * 128 + 96 + lane];
        unsigned m0 = __ballot_sync(0xffffffffu, v0 > 0);
        unsigned m1 = __ballot_sync(0xffffffffu, v1 > 0);
        unsigned m2 = __ballot_sync(0xffffffffu, v2 > 0);
        unsigned m3 = __ballot_sync(0xffffffffu, v3 > 0);
        if (lane == 0) {
            bp[w2 * 4 + 0] = m0; bp[w2 * 4 + 1] = m1;
            bp[w2 * 4 + 2] = m2; bp[w2 * 4 + 3] = m3;
        }
    }
}

// ---------------------------------------------------------------------------
// Kernel 4: tf32 MMA AV — round-12 proven config (plain launch_bounds(256),
// natural regs) + interleaved {B1,B2} factors: 2 x LDS.64 per ks (broadcast).
// ---------------------------------------------------------------------------
#define BPITCH   72
#define BUF_FL   (64 * BPITCH)
#define OFF_BB   0
#define OFF_B12F 36864                        // float2[2048] = 16 KB
#define OFF_WSUM 53248
#define OFF_BIAS 53760
#define SMEM_TOTAL 54016

__global__ void __launch_bounds__(256) attn_av_mma(const float* __restrict__ bias,
                                                   float* __restrict__ out) {
    extern __shared__ char smem[];
    const uint32_t sb = smem_u32(smem);
    const int b = blockIdx.z, h = blockIdx.y, i0 = blockIdx.x * 128;
    const int bh = b * H_ + h;
    const int t = threadIdx.x, wid = t >> 5, lane = t & 31;

    float* wsum_s = (float*)(smem + OFF_WSUM);
    float2* b12f  = (float2*)(smem + OFF_B12F);
    float* bias_s = (float*)(smem + OFF_BIAS);
    float* Bbuf   = (float*)(smem + OFF_BB);
    if (t < 16) *(float4*)&bias_s[t * 4] = *(const float4*)&bias[h * COUT_ + t * 4];

    // prologue: stage interleaved factor array (4096 floats = 16 KB)
    {
        const float* Bg = (const float*)(g_B12 + bh * N_);
        float* dst = (float*)b12f;
#pragma unroll
        for (int r = 0; r < 4; r++) {
            int q = (t + r * 256) * 4;
            *(float4*)&dst[q] = *(const float4*)&Bg[q];
        }
    }

    const int m0 = wid * 16;
    const int r0loc = m0 + (lane >> 2);
    const int r1loc = r0loc + 8;
    const int la = lane & 3;
    const int gn = lane >> 2;
    const float A1_0 = g_A1[bh * N_ + i0 + r0loc];
    const float A2_0 = g_A2[bh * N_ + i0 + r0loc];
    const float A1_1 = g_A1[bh * N_ + i0 + r1loc];
    const float A2_1 = g_A2[bh * N_ + i0 + r1loc];
    float lsum0 = 0.f, lsum1 = 0.f;

    const float* hT = g_htf + (size_t)bh * N_ * COUT_;
    const unsigned* bpr0 = g_bits + ((size_t)(b * N_ + i0 + r0loc)) * (N_ / 32);
    const unsigned* bpr1 = bpr0 + (size_t)8 * (N_ / 32);   // r1loc = r0loc + 8

    float acc[8][4] = {};

    // stage jt=0 into buffer 0
    {
#pragma unroll
        for (int r = 0; r < 4; r++) {
            int idx = t + r * 256;
            int row = idx >> 4, cq = idx & 15;
            cp_async16(sb + OFF_BB + (uint32_t)(row * BPITCH * 4 + cq * 16),
                       hT + (size_t)row * COUT_ + cq * 4);
        }
        CP_COMMIT();
    }

    for (int jt = 0; jt < 32; jt++) {
        const int j0 = jt * 64;
        const float* Bt = Bbuf + (jt & 1) * BUF_FL;

        CP_WAIT0();
        __syncthreads();

        if (jt + 1 < 32) {
            const int j0n = j0 + 64;
            const uint32_t bufn = sb + OFF_BB + (uint32_t)((jt + 1) & 1) * (BUF_FL * 4);
#pragma unroll
            for (int r = 0; r < 4; r++) {
                int idx = t + r * 256;
                int row = idx >> 4, cq = idx & 15;
                cp_async16(bufn + (uint32_t)(row * BPITCH * 4 + cq * 16),
                           hT + (size_t)(j0n + row) * COUT_ + cq * 4);
            }
            CP_COMMIT();
        }

        uint2 bitsA = *(const uint2*)&bpr0[jt * 2];
        uint2 bitsB = *(const uint2*)&bpr1[jt * 2];

#pragma unroll
        for (int ks = 0; ks < 8; ks++) {
            const int jl = ks * 8 + la;
            float2 fx = b12f[j0 + jl];        // {B1, B2} at j = jl    (LDS.64 bcast)
            float2 fy = b12f[j0 + jl + 4];    // {B1, B2} at j = jl+4
            unsigned wrd0 = (ks < 4) ? bitsA.x : bitsA.y;
            unsigned wrd1 = (ks < 4) ? bitsB.x : bitsB.y;
            const int sh = (ks & 3) * 8 + la;

            float wa0 = wfun(A1_0, A2_0, fx.x, fx.y, (wrd0 >> sh) & 1u);
            float wa2 = wfun(A1_0, A2_0, fy.x, fy.y, (wrd0 >> (sh + 4)) & 1u);
            float wb0 = wfun(A1_1, A2_1, fx.x, fx.y, (wrd1 >> sh) & 1u);
            float wb2 = wfun(A1_1, A2_1, fy.x, fy.y, (wrd1 >> (sh + 4)) & 1u);
            lsum0 += wa0 + wa2;
            lsum1 += wb0 + wb2;

            uint32_t afr[4];
            afr[0] = to_tf32(wa0);
            afr[1] = to_tf32(wb0);
            afr[2] = to_tf32(wa2);
            afr[3] = to_tf32(wb2);

            const float* Brow0 = Bt + (ks * 8 + la) * BPITCH + gn;
            const float* Brow1 = Brow0 + 4 * BPITCH;
#pragma unroll
            for (int q = 0; q < 8; q++) {
                uint32_t bf0 = __float_as_uint(Brow0[q * 8]);
                uint32_t bf1 = __float_as_uint(Brow1[q * 8]);
                mma_tf32(acc[q], afr, bf0, bf1);
            }
        }
    }

    lsum0 += __shfl_xor_sync(0xffffffffu, lsum0, 1);
    lsum0 += __shfl_xor_sync(0xffffffffu, lsum0, 2);
    lsum1 += __shfl_xor_sync(0xffffffffu, lsum1, 1);
    lsum1 += __shfl_xor_sync(0xffffffffu, lsum1, 2);
    if (la == 0) {
        wsum_s[r0loc] = lsum0;
        wsum_s[r1loc] = lsum1;
    }
    __syncthreads();

    const float inv0 = 1.f / wsum_s[r0loc];
    const float inv1 = 1.f / wsum_s[r1loc];
    float* op0 = out + ((size_t)(b * N_ + i0 + r0loc)) * (H_ * COUT_) + h * COUT_;
    float* op1 = out + ((size_t)(b * N_ + i0 + r1loc)) * (H_ * COUT_) + h * COUT_;
#pragma unroll
    for (int q = 0; q < 8; q++) {
        int col = q * 8 + la * 2;
        float bx = bias_s[col], by = bias_s[col + 1];
        float2 o0, o1;
        o0.x = fmaxf(acc[q][0] * inv0 + bx, 0.f);
        o0.y = fmaxf(acc[q][1] * inv0 + by, 0.f);
        o1.x = fmaxf(acc[q][2] * inv1 + bx, 0.f);
        o1.y = fmaxf(acc[q][3] * inv1 + by, 0.f);
        *(float2*)&op0[col] = o0;
        *(float2*)&op1[col] = o1;
    }
}

// ---------------------------------------------------------------------------
extern "C" void kernel_launch(void* const* d_in, const int* in_sizes, int n_in,
                              void* d_out, int out_size) {
    const float* x    = (const float*)d_in[0];
    const int*   adj  = (const int*)  d_in[1];
    const float* W    = (const float*)d_in[2];
    const float* a    = (const float*)d_in[3];
    const float* bias = (const float*)d_in[4];
    float* out = (float*)d_out;

    cudaFuncSetAttribute(attn_av_mma, cudaFuncAttributeMaxDynamicSharedMemorySize,
                         SMEM_TOTAL);

    adj_bits_k<<<(B_ * N_) / 8, 256>>>(adj);

    dim3 g1(N_ / 64, 2, B_);
    gemm_hidden_tc<<<g1, 256>>>(x, W, a);

    s2max_k<<<B_ * H_, 256>>>();
    factors_k<<<B_ * H_ * 8, 256>>>();

    dim3 g4(N_ / 128, H_, B_);
    attn_av_mma<<<g4, 256, SMEM_TOTAL>>>(bias, out);
}